// round 4
// baseline (speedup 1.0000x reference)
#include <cuda_runtime.h>

// PPO loss + GAE for B=4096, T=2048.
//
// Pipeline (5 launches, all graph-capturable, no allocations):
//   0. init:     zero the double accumulators (graph is replayed; must be
//                deterministic per replay).
//   1. gae:      one warp per row. Warp-parallel suffix scan of the affine
//                recurrence adv[t] = d[t] + c[t]*adv[t+1] over 32-element
//                segments with a serial carry across the 64 segments.
//                Writes adv to a __device__ scratch and accumulates
//                sum(adv), sum(adv^2) in doubles (block-level atomics).
//                Note value_loss = mean((returns - values)^2) = mean(adv^2),
//                so it falls out of this pass for free.
//   2. stats:    1 thread: mean and 1/(std+eps) (ddof=1) from the sums.
//   3. loss:     grid-stride float4 pass over adv/old_probs/curr_probs:
//                ppo surrogate (with normalized adv) + entropy sums.
//   4. finalize: 1 thread writes the 4 output scalars.

namespace {
constexpr int B = 4096;
constexpr int T = 2048;
constexpr long long NTOT = (long long)B * T;          // 8388608
constexpr float GAMMA = 0.99f;
constexpr float LAM   = 0.95f;
constexpr float CLIPP = 0.2f;
constexpr float EPSF  = 1e-9f;
}

__device__ float  g_adv[(size_t)B * T];   // 32 MB scratch for unnormalized advantages
__device__ double g_sum, g_sumsq, g_ppo, g_ent;
__device__ float  g_mean, g_rstd;

__global__ void init_kernel() {
    g_sum = 0.0; g_sumsq = 0.0; g_ppo = 0.0; g_ent = 0.0;
}

__global__ __launch_bounds__(256) void gae_kernel(
    const float* __restrict__ rewards,
    const float* __restrict__ values,
    const float* __restrict__ masks)
{
    const int gwarp = (blockIdx.x * blockDim.x + threadIdx.x) >> 5;
    const int lane  = threadIdx.x & 31;
    const int wid   = threadIdx.x >> 5;

    float lsum = 0.f, lsq = 0.f;

    if (gwarp < B) {
        const float* rr = rewards + (size_t)gwarp * T;
        const float* vr = values  + (size_t)gwarp * (T + 1);
        const float* mr = masks   + (size_t)gwarp * T;
        float*       ar = g_adv   + (size_t)gwarp * T;

        float carry = 0.f;   // adv at t = segment_end + 1 (adv[T] == 0)

        for (int seg = T / 32 - 1; seg >= 0; --seg) {
            const int t  = seg * 32 + lane;
            const float r  = rr[t];
            const float v  = vr[t];
            const float vn = vr[t + 1];
            const float m  = mr[t];

            // adv[t] = d + c * adv[t+1]
            float c = (GAMMA * LAM) * m;
            float d = fmaf(GAMMA * vn, m, r) - v;   // r + gamma*v_next*m - v

            // Suffix composition: after the scan, lane i holds the affine map
            // for elements [i..31] applied to the incoming carry.
            // (A o B)(x) = A.c*(B.c*x + B.d) + A.d
            #pragma unroll
            for (int off = 1; off < 32; off <<= 1) {
                const float c2 = __shfl_down_sync(0xffffffffu, c, off);
                const float d2 = __shfl_down_sync(0xffffffffu, d, off);
                if (lane + off < 32) {
                    d = fmaf(c, d2, d);
                    c = c * c2;
                }
            }

            const float adv = fmaf(c, carry, d);
            ar[t] = adv;
            lsum += adv;
            lsq = fmaf(adv, adv, lsq);

            carry = __shfl_sync(0xffffffffu, adv, 0);  // adv at segment start
        }
    }

    // warp reduce (each thread holds a 64-element partial -> fp32 is plenty)
    #pragma unroll
    for (int off = 16; off; off >>= 1) {
        lsum += __shfl_down_sync(0xffffffffu, lsum, off);
        lsq  += __shfl_down_sync(0xffffffffu, lsq,  off);
    }

    __shared__ double s_sum[8], s_sq[8];
    if (lane == 0) { s_sum[wid] = (double)lsum; s_sq[wid] = (double)lsq; }
    __syncthreads();
    if (threadIdx.x == 0) {
        double bs = 0.0, bq = 0.0;
        #pragma unroll
        for (int i = 0; i < 8; ++i) { bs += s_sum[i]; bq += s_sq[i]; }
        atomicAdd(&g_sum,   bs);
        atomicAdd(&g_sumsq, bq);
    }
}

__global__ void stats_kernel() {
    const double n    = (double)NTOT;
    const double mean = g_sum / n;
    const double var  = (g_sumsq - g_sum * g_sum / n) / (n - 1.0);  // ddof=1
    g_mean = (float)mean;
    g_rstd = (float)(1.0 / (sqrt(var) + (double)EPSF));
}

__global__ __launch_bounds__(256) void loss_kernel(
    const float* __restrict__ old_p,
    const float* __restrict__ curr_p)
{
    const float mean = g_mean;
    const float rstd = g_rstd;

    const int n4 = (int)(NTOT / 4);
    const float4* a4 = (const float4*)g_adv;
    const float4* o4 = (const float4*)old_p;
    const float4* c4 = (const float4*)curr_p;

    float ppo = 0.f, ent = 0.f;

    for (int i = blockIdx.x * blockDim.x + threadIdx.x; i < n4;
         i += gridDim.x * blockDim.x) {
        const float4 a = a4[i];
        const float4 o = o4[i];
        const float4 c = c4[i];
        const float* av = (const float*)&a;
        const float* ov = (const float*)&o;
        const float* cv = (const float*)&c;
        #pragma unroll
        for (int k = 0; k < 4; ++k) {
            const float ratio = __fdividef(cv[k], ov[k] + EPSF);
            const float adv   = (av[k] - mean) * rstd;
            const float cl    = fminf(fmaxf(ratio, 1.f - CLIPP), 1.f + CLIPP);
            ppo += fminf(ratio * adv, cl * adv);
            ent  = fmaf(cv[k], __logf(cv[k] + EPSF), ent);
        }
    }

    #pragma unroll
    for (int off = 16; off; off >>= 1) {
        ppo += __shfl_down_sync(0xffffffffu, ppo, off);
        ent += __shfl_down_sync(0xffffffffu, ent, off);
    }

    __shared__ double s_p[8], s_e[8];
    const int lane = threadIdx.x & 31, wid = threadIdx.x >> 5;
    if (lane == 0) { s_p[wid] = (double)ppo; s_e[wid] = (double)ent; }
    __syncthreads();
    if (threadIdx.x == 0) {
        double bp = 0.0, be = 0.0;
        #pragma unroll
        for (int i = 0; i < 8; ++i) { bp += s_p[i]; be += s_e[i]; }
        atomicAdd(&g_ppo, bp);
        atomicAdd(&g_ent, be);
    }
}

__global__ void finalize_kernel(float* __restrict__ out) {
    const double n   = (double)NTOT;
    const double ppo = -(g_ppo / n);
    const double vls = 0.5  * (g_sumsq / n);   // value_loss = mean(adv^2)
    const double ent = -0.01 * (g_ent / n);
    out[0] = (float)(ppo + vls + ent);
    out[1] = (float)ppo;
    out[2] = (float)vls;
    out[3] = (float)ent;
}

extern "C" void kernel_launch(void* const* d_in, const int* in_sizes, int n_in,
                              void* d_out, int out_size)
{
    // Identify `values` by its unique size B*(T+1); the remaining inputs keep
    // their metadata order: rewards, ref_probs (unused), old_probs,
    // curr_probs, masks.
    int vi = 1;
    for (int i = 0; i < n_in; ++i)
        if (in_sizes[i] == B * (T + 1)) { vi = i; break; }

    const float* others[8];
    int k = 0;
    for (int i = 0; i < n_in; ++i)
        if (i != vi) others[k++] = (const float*)d_in[i];

    const float* rewards = others[0];
    // others[1] = ref_probs, unused by the reference
    const float* old_p   = others[2];
    const float* curr_p  = others[3];
    const float* masks   = others[4];
    const float* values  = (const float*)d_in[vi];

    init_kernel<<<1, 1>>>();
    gae_kernel<<<B / 8, 256>>>(rewards, values, masks);   // 8 warps (rows) per block
    stats_kernel<<<1, 1>>>();
    loss_kernel<<<1184, 256>>>(old_p, curr_p);            // 148 SMs * 8 CTAs
    finalize_kernel<<<1, 1>>>((float*)d_out);
}

// round 5
// speedup vs baseline: 1.5491x; 1.5491x over previous
#include <cuda_runtime.h>

// PPO loss + GAE, B=4096 x T=2048.
//
// 3 launches (graph-capturable, allocation-free):
//   1. gae:      one warp per row. Blocked affine suffix scan: each lane
//                locally composes 8 contiguous steps of
//                adv[t] = d[t] + c[t]*adv[t+1], then a 5-round warp scan
//                covers 256 timesteps per segment (8 segments total, vs 64
//                in the previous version). Writes unnormalized adv to a
//                __device__ scratch; accumulates sum(adv), sum(adv^2).
//                value_loss = mean((returns-values)^2) = mean(adv^2) free.
//   2. loss:     mean/rstd derived per-block from the accumulators, then a
//                grid-stride paired-float4 pass computing the clipped PPO
//                surrogate + entropy sums.
//   3. finalize: writes the 4 scalars and RESETS the accumulators so every
//                graph replay starts from the same (zero) state.

namespace {
constexpr int B = 4096;
constexpr int T = 2048;
constexpr long long NTOT = (long long)B * T;   // 8388608
constexpr float GAMMA = 0.99f;
constexpr float LAM   = 0.95f;
constexpr float GL    = GAMMA * LAM;
constexpr float CLIPP = 0.2f;
constexpr float EPSF  = 1e-9f;
constexpr int CHUNK = 8;                 // timesteps per lane per segment
constexpr int SEG   = 32 * CHUNK;        // 256 timesteps per warp scan
constexpr int NSEG  = T / SEG;           // 8
}

__device__ float  g_adv[(size_t)B * T];  // 32 MB unnormalized advantages
__device__ double g_sum, g_sumsq, g_ppo, g_ent;   // zero-initialized

// ---------------------------------------------------------------- pass 1
__global__ __launch_bounds__(128) void gae_kernel(
    const float* __restrict__ rewards,
    const float* __restrict__ values,
    const float* __restrict__ masks)
{
    const int gwarp = (blockIdx.x * blockDim.x + threadIdx.x) >> 5;  // row
    const int lane  = threadIdx.x & 31;
    const int wid   = threadIdx.x >> 5;
    const unsigned FULL = 0xffffffffu;

    float lsum = 0.f, lsq = 0.f;

    if (gwarp < B) {
        const float* rr = rewards + (size_t)gwarp * T;
        const float* vr = values  + (size_t)gwarp * (T + 1);
        const float* mr = masks   + (size_t)gwarp * T;
        float*       ar = g_adv   + (size_t)gwarp * T;

        float carry = 0.f;   // adv just past the current segment (adv[T]=0)

        for (int seg = NSEG - 1; seg >= 0; --seg) {
            const int base = seg * SEG + lane * CHUNK;

            // streaming loads (read-once data; keep L2 room for g_adv)
            const float4 ra = __ldcs((const float4*)(rr + base));
            const float4 rb = __ldcs((const float4*)(rr + base + 4));
            const float4 ma = __ldcs((const float4*)(mr + base));
            const float4 mb = __ldcs((const float4*)(mr + base + 4));
            float v[CHUNK + 1];
            #pragma unroll
            for (int j = 0; j <= CHUNK; ++j) v[j] = __ldcs(vr + base + j);

            const float r_[CHUNK] = {ra.x, ra.y, ra.z, ra.w, rb.x, rb.y, rb.z, rb.w};
            const float m_[CHUNK] = {ma.x, ma.y, ma.z, ma.w, mb.x, mb.y, mb.z, mb.w};

            float c[CHUNK], d[CHUNK];
            #pragma unroll
            for (int j = 0; j < CHUNK; ++j) {
                c[j] = GL * m_[j];
                d[j] = fmaf(GAMMA * v[j + 1], m_[j], r_[j]) - v[j];
            }

            // local suffix composition over this lane's 8 steps:
            // (C,D) maps adv[base+8] -> adv[base]
            float C = c[CHUNK - 1], D = d[CHUNK - 1];
            #pragma unroll
            for (int j = CHUNK - 2; j >= 0; --j) {
                D = fmaf(c[j], D, d[j]);
                C = c[j] * C;
            }

            // warp inclusive suffix scan of the 32 per-lane maps
            #pragma unroll
            for (int off = 1; off < 32; off <<= 1) {
                const float C2 = __shfl_down_sync(FULL, C, off);
                const float D2 = __shfl_down_sync(FULL, D, off);
                if (lane + off < 32) {
                    D = fmaf(C, D2, D);
                    C = C * C2;
                }
            }

            // x = (maps of lanes > me)(carry) = adv at my chunk's end+1
            const float Cx = __shfl_down_sync(FULL, C, 1);
            const float Dx = __shfl_down_sync(FULL, D, 1);
            float x = (lane == 31) ? carry : fmaf(Cx, carry, Dx);

            // unroll my 8 advantages (reverse time)
            float a[CHUNK];
            #pragma unroll
            for (int j = CHUNK - 1; j >= 0; --j) {
                a[j] = fmaf(c[j], x, d[j]);
                x = a[j];
            }
            // carry for the next (earlier) segment = lane 0's adv[base]
            carry = __shfl_sync(FULL, x, 0);

            float4 oa = make_float4(a[0], a[1], a[2], a[3]);
            float4 ob = make_float4(a[4], a[5], a[6], a[7]);
            *(float4*)(ar + base)     = oa;
            *(float4*)(ar + base + 4) = ob;

            #pragma unroll
            for (int j = 0; j < CHUNK; ++j) {
                lsum += a[j];
                lsq = fmaf(a[j], a[j], lsq);
            }
        }
    }

    #pragma unroll
    for (int off = 16; off; off >>= 1) {
        lsum += __shfl_down_sync(FULL, lsum, off);
        lsq  += __shfl_down_sync(FULL, lsq,  off);
    }

    __shared__ double s_sum[4], s_sq[4];
    if (lane == 0) { s_sum[wid] = (double)lsum; s_sq[wid] = (double)lsq; }
    __syncthreads();
    if (threadIdx.x == 0) {
        double bs = 0.0, bq = 0.0;
        #pragma unroll
        for (int i = 0; i < 4; ++i) { bs += s_sum[i]; bq += s_sq[i]; }
        atomicAdd(&g_sum,   bs);
        atomicAdd(&g_sumsq, bq);
    }
}

// ---------------------------------------------------------------- pass 2
__global__ __launch_bounds__(256) void loss_kernel(
    const float* __restrict__ old_p,
    const float* __restrict__ curr_p)
{
    __shared__ float sh_mean, sh_rstd;
    if (threadIdx.x == 0) {
        const double n    = (double)NTOT;
        const double mean = g_sum / n;
        const double var  = (g_sumsq - g_sum * g_sum / n) / (n - 1.0);  // ddof=1
        sh_mean = (float)mean;
        sh_rstd = (float)(1.0 / (sqrt(var) + (double)EPSF));
    }
    __syncthreads();
    const float mean = sh_mean, rstd = sh_rstd;

    const int n4 = (int)(NTOT / 4);
    const float4* a4 = (const float4*)g_adv;
    const float4* o4 = (const float4*)old_p;
    const float4* c4 = (const float4*)curr_p;

    float ppo = 0.f, ent = 0.f;
    const int stride = gridDim.x * blockDim.x;

    for (int i = blockIdx.x * blockDim.x + threadIdx.x; i < n4; i += 2 * stride) {
        const int j = i + stride;
        const bool hasj = (j < n4);

        // issue all loads up front (MLP 6)
        const float4 a0 = a4[i];
        const float4 o0 = __ldcs(o4 + i);
        const float4 cc0 = __ldcs(c4 + i);
        float4 a1, o1, cc1;
        if (hasj) {
            a1  = a4[j];
            o1  = __ldcs(o4 + j);
            cc1 = __ldcs(c4 + j);
        }

        const float* av0 = (const float*)&a0;
        const float* ov0 = (const float*)&o0;
        const float* cv0 = (const float*)&cc0;
        #pragma unroll
        for (int k = 0; k < 4; ++k) {
            const float ratio = __fdividef(cv0[k], ov0[k] + EPSF);
            const float adv   = (av0[k] - mean) * rstd;
            const float cl    = fminf(fmaxf(ratio, 1.f - CLIPP), 1.f + CLIPP);
            ppo += fminf(ratio * adv, cl * adv);
            ent  = fmaf(cv0[k], __logf(cv0[k] + EPSF), ent);
        }
        if (hasj) {
            const float* av1 = (const float*)&a1;
            const float* ov1 = (const float*)&o1;
            const float* cv1 = (const float*)&cc1;
            #pragma unroll
            for (int k = 0; k < 4; ++k) {
                const float ratio = __fdividef(cv1[k], ov1[k] + EPSF);
                const float adv   = (av1[k] - mean) * rstd;
                const float cl    = fminf(fmaxf(ratio, 1.f - CLIPP), 1.f + CLIPP);
                ppo += fminf(ratio * adv, cl * adv);
                ent  = fmaf(cv1[k], __logf(cv1[k] + EPSF), ent);
            }
        }
    }

    #pragma unroll
    for (int off = 16; off; off >>= 1) {
        ppo += __shfl_down_sync(0xffffffffu, ppo, off);
        ent += __shfl_down_sync(0xffffffffu, ent, off);
    }

    __shared__ double s_p[8], s_e[8];
    const int lane = threadIdx.x & 31, wid = threadIdx.x >> 5;
    if (lane == 0) { s_p[wid] = (double)ppo; s_e[wid] = (double)ent; }
    __syncthreads();
    if (threadIdx.x == 0) {
        double bp = 0.0, be = 0.0;
        #pragma unroll
        for (int i = 0; i < 8; ++i) { bp += s_p[i]; be += s_e[i]; }
        atomicAdd(&g_ppo, bp);
        atomicAdd(&g_ent, be);
    }
}

// ---------------------------------------------------------------- pass 3
__global__ void finalize_kernel(float* __restrict__ out) {
    const double n   = (double)NTOT;
    const double ppo = -(g_ppo / n);
    const double vls = 0.5  * (g_sumsq / n);   // value_loss = mean(adv^2)
    const double ent = -0.01 * (g_ent / n);
    out[0] = (float)(ppo + vls + ent);
    out[1] = (float)ppo;
    out[2] = (float)vls;
    out[3] = (float)ent;
    // reset for the next graph replay (deterministic start state)
    g_sum = 0.0; g_sumsq = 0.0; g_ppo = 0.0; g_ent = 0.0;
}

extern "C" void kernel_launch(void* const* d_in, const int* in_sizes, int n_in,
                              void* d_out, int out_size)
{
    // `values` has the unique size B*(T+1); everything else keeps metadata
    // order: rewards, ref_probs (unused), old_probs, curr_probs, masks.
    int vi = 1;
    for (int i = 0; i < n_in; ++i)
        if (in_sizes[i] == B * (T + 1)) { vi = i; break; }

    const float* others[8];
    int k = 0;
    for (int i = 0; i < n_in; ++i)
        if (i != vi) others[k++] = (const float*)d_in[i];

    const float* rewards = others[0];
    const float* old_p   = others[2];
    const float* curr_p  = others[3];
    const float* masks   = others[4];
    const float* values  = (const float*)d_in[vi];

    gae_kernel<<<B / 4, 128>>>(rewards, values, masks);   // 1024 CTAs, 1 warp/row
    loss_kernel<<<1184, 256>>>(old_p, curr_p);
    finalize_kernel<<<1, 1>>>((float*)d_out);
}